// round 15
// baseline (speedup 1.0000x reference)
#include <cuda_runtime.h>
#include <math.h>
#include <stdint.h>

#define EMB   1024
#define HS    64
#define TSEQ  4096
#define BATCH 4
#define MTOT  (BATCH * TSEQ)   // 16384 rows

#define NQT    64              // 64-row q tiles per batch
#define CHUNK  8               // 64-row kv-tiles per partial job
#define NJOBS  288             // sum_{q=0}^{63} (q/8+1)
#define NJOBS_T (NJOBS * BATCH)

// Scratch (device globals: allocation-free rule)
__device__ unsigned short g_qh[MTOT * HS], g_ql[MTOT * HS];   // Q hi/lo bf16, natural
__device__ unsigned short g_kh[MTOT * HS], g_kl[MTOT * HS];   // K hi/lo bf16, natural
__device__ unsigned short g_vth[BATCH * HS * TSEQ];           // V hi bf16, transposed [b][h][t]
__device__ unsigned short g_vtl[BATCH * HS * TSEQ];           // V lo
__device__ unsigned short g_wth[3 * HS * EMB];                // W hi bf16, transposed [w][n][k]
__device__ unsigned short g_wtl[3 * HS * EMB];                // W lo
__device__ float g_po[NJOBS_T * 64 * HS];    // partial O [slot][row][64]
__device__ float g_pm[NJOBS_T * 64];         // partial row max
__device__ float g_pl[NJOBS_T * 64];         // partial row sum

// ---- bf16 split: pack (x,y) -> bf16x2 hi + lo residual ----
__device__ __forceinline__ void split2(float x, float y, unsigned &hp, unsigned &lp) {
    asm("cvt.rn.bf16x2.f32 %0, %1, %2;" : "=r"(hp) : "f"(y), "f"(x));
    float xh = __uint_as_float(hp << 16);
    float yh = __uint_as_float(hp & 0xffff0000u);
    asm("cvt.rn.bf16x2.f32 %0, %1, %2;" : "=r"(lp) : "f"(y - yh), "f"(x - xh));
}

// ---- warp mma m16n8k16 bf16 -> f32 accumulate ----
#define MMA_BF16(c, a, b0, b1) \
    asm("mma.sync.aligned.m16n8k16.row.col.f32.bf16.bf16.f32 " \
        "{%0,%1,%2,%3},{%4,%5,%6,%7},{%8,%9},{%0,%1,%2,%3};" \
        : "+f"((c)[0]), "+f"((c)[1]), "+f"((c)[2]), "+f"((c)[3]) \
        : "r"((a)[0]), "r"((a)[1]), "r"((a)[2]), "r"((a)[3]), "r"(b0), "r"(b1))

// ---------------------------------------------------------------------------
// Kernel 0: split W into transposed bf16 hi/lo (verbatim R13).
// ---------------------------------------------------------------------------
__global__ __launch_bounds__(256) void wsplit_kernel(
    const float* __restrict__ Wq,
    const float* __restrict__ Wk,
    const float* __restrict__ Wv)
{
    int idx = blockIdx.x * 256 + threadIdx.x;
    if (idx >= 3 * EMB * HS) return;
    int w   = idx >> 16;
    int rem = idx & 65535;
    int k   = rem >> 6;
    int n   = rem & 63;
    const float* W = (w == 0) ? Wq : (w == 1) ? Wk : Wv;
    float x = W[k * HS + n];
    unsigned short h, l;
    asm("cvt.rn.bf16.f32 %0, %1;" : "=h"(h) : "f"(x));
    float xh = __uint_as_float(((unsigned)h) << 16);
    float xl = x - xh;
    asm("cvt.rn.bf16.f32 %0, %1;" : "=h"(l) : "f"(xl));
    g_wth[((size_t)w * HS + n) * EMB + k] = h;
    g_wtl[((size_t)w * HS + n) * EMB + k] = l;
}

// ---------------------------------------------------------------------------
// Kernel 1: fused QKV projection on tensor cores (verbatim R13 winner).
// ---------------------------------------------------------------------------
#define XKS 72
#define QKV_SMEM_BYTES ((2 * 64 * XKS + 2 * 3 * 64 * XKS) * 2)

__global__ __launch_bounds__(128, 2) void qkv_kernel(const float* __restrict__ X)
{
    extern __shared__ __align__(16) unsigned short sm[];
    unsigned short* Xh = sm;
    unsigned short* Xl = Xh + 64 * XKS;
    unsigned short* Wh = Xl + 64 * XKS;
    unsigned short* Wl = Wh + 3 * 64 * XKS;

    const int tid  = threadIdx.x;
    const int wid  = tid >> 5;
    const int lane = tid & 31;
    const int lq   = lane >> 2;
    const int lr   = lane & 3;
    const int m0   = blockIdx.x * 64;

    float c[3][8][4];
#pragma unroll
    for (int w3 = 0; w3 < 3; w3++)
#pragma unroll
        for (int nt = 0; nt < 8; nt++)
#pragma unroll
            for (int j = 0; j < 4; j++) c[w3][nt][j] = 0.0f;

    for (int k0 = 0; k0 < EMB; k0 += 64) {
#pragma unroll
        for (int t = 0; t < 8; t++) {
            int idx = tid + 128 * t;
            int row = idx >> 4;
            int cg  = idx & 15;
            float4 v = *(const float4*)&X[(size_t)(m0 + row) * EMB + k0 + 4 * cg];
            unsigned h01, l01, h23, l23;
            split2(v.x, v.y, h01, l01);
            split2(v.z, v.w, h23, l23);
            *(unsigned*)&Xh[row * XKS + 4 * cg]     = h01;
            *(unsigned*)&Xh[row * XKS + 4 * cg + 2] = h23;
            *(unsigned*)&Xl[row * XKS + 4 * cg]     = l01;
            *(unsigned*)&Xl[row * XKS + 4 * cg + 2] = l23;
        }
#pragma unroll
        for (int t = 0; t < 24; t++) {
            int idx  = tid + 128 * t;
            int wh   = idx >> 9;
            int w3   = wh >> 1;
            int half = wh & 1;
            int rem  = idx & 511;
            int n    = rem >> 3;
            int cc   = rem & 7;
            const unsigned short* src = half ? g_wtl : g_wth;
            unsigned short* dst = half ? Wl : Wh;
            *(float4*)&dst[(w3 * 64 + n) * XKS + 8 * cc] =
                *(const float4*)&src[((size_t)w3 * 64 + n) * EMB + k0 + 8 * cc];
        }
        __syncthreads();

        unsigned ah[4][4], al[4][4];
        int r = 16 * wid + lq;
#pragma unroll
        for (int ks = 0; ks < 4; ks++) {
            int col = 2 * lr + 16 * ks;
            ah[ks][0] = *(const unsigned*)&Xh[r * XKS + col];
            ah[ks][1] = *(const unsigned*)&Xh[(r + 8) * XKS + col];
            ah[ks][2] = *(const unsigned*)&Xh[r * XKS + col + 8];
            ah[ks][3] = *(const unsigned*)&Xh[(r + 8) * XKS + col + 8];
            al[ks][0] = *(const unsigned*)&Xl[r * XKS + col];
            al[ks][1] = *(const unsigned*)&Xl[(r + 8) * XKS + col];
            al[ks][2] = *(const unsigned*)&Xl[r * XKS + col + 8];
            al[ks][3] = *(const unsigned*)&Xl[(r + 8) * XKS + col + 8];
        }

#pragma unroll
        for (int w3 = 0; w3 < 3; w3++)
#pragma unroll
            for (int nt = 0; nt < 8; nt++)
#pragma unroll
                for (int ks = 0; ks < 4; ks++) {
                    int base = (w3 * 64 + 8 * nt + lq) * XKS + 2 * lr + 16 * ks;
                    unsigned bh0 = *(const unsigned*)&Wh[base];
                    unsigned bh1 = *(const unsigned*)&Wh[base + 8];
                    unsigned bl0 = *(const unsigned*)&Wl[base];
                    unsigned bl1 = *(const unsigned*)&Wl[base + 8];
                    MMA_BF16(c[w3][nt], ah[ks], bh0, bh1);
                    MMA_BF16(c[w3][nt], ah[ks], bl0, bl1);
                    MMA_BF16(c[w3][nt], al[ks], bh0, bh1);
                }
        __syncthreads();
    }

    const int r0 = m0 + 16 * wid + lq;
    const int bb = r0 >> 12;
    const int t0 = r0 & 4095;
#pragma unroll
    for (int nt = 0; nt < 8; nt++) {
        int n0 = 8 * nt + 2 * lr;
        unsigned hp, lp;
        split2(c[0][nt][0], c[0][nt][1], hp, lp);
        *(unsigned*)&g_qh[(size_t)r0 * HS + n0] = hp;
        *(unsigned*)&g_ql[(size_t)r0 * HS + n0] = lp;
        split2(c[0][nt][2], c[0][nt][3], hp, lp);
        *(unsigned*)&g_qh[(size_t)(r0 + 8) * HS + n0] = hp;
        *(unsigned*)&g_ql[(size_t)(r0 + 8) * HS + n0] = lp;
        split2(c[1][nt][0], c[1][nt][1], hp, lp);
        *(unsigned*)&g_kh[(size_t)r0 * HS + n0] = hp;
        *(unsigned*)&g_kl[(size_t)r0 * HS + n0] = lp;
        split2(c[1][nt][2], c[1][nt][3], hp, lp);
        *(unsigned*)&g_kh[(size_t)(r0 + 8) * HS + n0] = hp;
        *(unsigned*)&g_kl[(size_t)(r0 + 8) * HS + n0] = lp;
        split2(c[2][nt][0], c[2][nt][1], hp, lp);
        g_vth[((size_t)bb * HS + n0) * TSEQ + t0]     = (unsigned short)hp;
        g_vth[((size_t)bb * HS + n0 + 1) * TSEQ + t0] = (unsigned short)(hp >> 16);
        g_vtl[((size_t)bb * HS + n0) * TSEQ + t0]     = (unsigned short)lp;
        g_vtl[((size_t)bb * HS + n0 + 1) * TSEQ + t0] = (unsigned short)(lp >> 16);
        split2(c[2][nt][2], c[2][nt][3], hp, lp);
        g_vth[((size_t)bb * HS + n0) * TSEQ + t0 + 8]     = (unsigned short)hp;
        g_vth[((size_t)bb * HS + n0 + 1) * TSEQ + t0 + 8] = (unsigned short)(hp >> 16);
        g_vtl[((size_t)bb * HS + n0) * TSEQ + t0 + 8]     = (unsigned short)lp;
        g_vtl[((size_t)bb * HS + n0 + 1) * TSEQ + t0 + 8] = (unsigned short)(lp >> 16);
    }
}

// ---------------------------------------------------------------------------
// Kernel 2: split-KV flash attention, mma.sync bf16x3 (R12-verified math),
// BM=64 q-rows x 64 kv per tile, 128 threads = 4 warps; warp w owns rows
// [16w,16w+16). 3 CTAs/SM (36.8KB smem, regs<=170) -> 3 independent
// tile-phases per SM to fill tensor-pipe gaps during softmax.
// Jobs: per batch qt=63..0 (LPT), nc(qt)=qt/8+1 chunks of CHUNK=8 kv-tiles.
// ---------------------------------------------------------------------------
#define KST 72    // ushort stride of K/Vt smem rows
#define ATTN_SMEM_BYTES (4 * 64 * KST * 2)   // Kh,Kl,Vh,Vl = 36864

__global__ __launch_bounds__(128, 3) void attn_partial_kernel(void)
{
    extern __shared__ __align__(16) unsigned short smh[];
    unsigned short* Kh = smh;               // [64 kv][KST]  natural (h contiguous)
    unsigned short* Kl = Kh + 64 * KST;
    unsigned short* Vh = Kl + 64 * KST;     // [64 h][KST]   transposed (kv contiguous)
    unsigned short* Vl = Vh + 64 * KST;

    const int b = blockIdx.x & 3;
    int rem = blockIdx.x >> 2;
    int qt = 63;
    for (;;) { int nc = (qt >> 3) + 1; if (rem < nc) break; rem -= nc; --qt; }
    const int c = rem;
    const int kt0 = CHUNK * c;
    const int kt1 = min(CHUNK * c + CHUNK, qt + 1);
    int pre = 0;
    for (int qq = 63; qq > qt; --qq) pre += (qq >> 3) + 1;
    const int slot = b * NJOBS + pre + c;

    const int tid  = threadIdx.x;
    const int w    = tid >> 5;     // 0..3
    const int lane = tid & 31;
    const int lq   = lane >> 2;    // 0..7
    const int lr   = lane & 3;     // 0..3

    const size_t qrow0 = (size_t)b * TSEQ + qt * 64 + 16 * w + lq;
    const size_t kbase = (size_t)b * TSEQ;

    // ---- load Q fragments (hi/lo) once ----
    unsigned ah[4][4], al[4][4];
#pragma unroll
    for (int ks = 0; ks < 4; ks++) {
        int col = 2 * lr + 16 * ks;
        ah[ks][0] = *(const unsigned*)&g_qh[qrow0 * HS + col];
        ah[ks][1] = *(const unsigned*)&g_qh[(qrow0 + 8) * HS + col];
        ah[ks][2] = *(const unsigned*)&g_qh[qrow0 * HS + col + 8];
        ah[ks][3] = *(const unsigned*)&g_qh[(qrow0 + 8) * HS + col + 8];
        al[ks][0] = *(const unsigned*)&g_ql[qrow0 * HS + col];
        al[ks][1] = *(const unsigned*)&g_ql[(qrow0 + 8) * HS + col];
        al[ks][2] = *(const unsigned*)&g_ql[qrow0 * HS + col + 8];
        al[ks][3] = *(const unsigned*)&g_ql[(qrow0 + 8) * HS + col + 8];
    }

    float m0 = -1e30f, m1 = -1e30f, l0 = 0.0f, l1 = 0.0f;
    float o_[8][4];
#pragma unroll
    for (int nt = 0; nt < 8; nt++)
#pragma unroll
        for (int j = 0; j < 4; j++) o_[nt][j] = 0.0f;

    for (int kt = kt0; kt < kt1; kt++) {
        // ---- stage K (natural) and V (transposed) hi/lo tiles ----
#pragma unroll
        for (int it = 0; it < 4; it++) {
            int idx = tid + 128 * it;     // 0..511
            int row = idx >> 3;           // 0..63
            int cc  = idx & 7;            // 0..7
            size_t kg = (kbase + (size_t)kt * 64 + row) * HS + 8 * cc;
            *(float4*)&Kh[row * KST + 8 * cc] = *(const float4*)&g_kh[kg];
            *(float4*)&Kl[row * KST + 8 * cc] = *(const float4*)&g_kl[kg];
            size_t vg = ((size_t)(b * HS + row)) * TSEQ + (size_t)kt * 64 + 8 * cc;
            *(float4*)&Vh[row * KST + 8 * cc] = *(const float4*)&g_vth[vg];
            *(float4*)&Vl[row * KST + 8 * cc] = *(const float4*)&g_vtl[vg];
        }
        __syncthreads();

        // ---- S = Q@K^T (bf16x3) ----
        float s[8][4];
#pragma unroll
        for (int nt = 0; nt < 8; nt++)
#pragma unroll
            for (int j = 0; j < 4; j++) s[nt][j] = 0.0f;

#pragma unroll
        for (int nt = 0; nt < 8; nt++) {
            int base = (8 * nt + lq) * KST + 2 * lr;
#pragma unroll
            for (int ks = 0; ks < 4; ks++) {
                int o = base + 16 * ks;
                unsigned bh0 = *(const unsigned*)&Kh[o];
                unsigned bh1 = *(const unsigned*)&Kh[o + 8];
                unsigned bl0 = *(const unsigned*)&Kl[o];
                unsigned bl1 = *(const unsigned*)&Kl[o + 8];
                MMA_BF16(s[nt], ah[ks], bh0, bh1);
                MMA_BF16(s[nt], ah[ks], bl0, bl1);
                MMA_BF16(s[nt], al[ks], bh0, bh1);
            }
        }

        // ---- causal mask (only the kt==qt diagonal tile) ----
        if (kt == qt) {
            int rl0 = 16 * w + lq;
            int rl1 = rl0 + 8;
#pragma unroll
            for (int nt = 0; nt < 8; nt++) {
                int cl = 8 * nt + 2 * lr;
                if (cl     > rl0) s[nt][0] = -1e30f;
                if (cl + 1 > rl0) s[nt][1] = -1e30f;
                if (cl     > rl1) s[nt][2] = -1e30f;
                if (cl + 1 > rl1) s[nt][3] = -1e30f;
            }
        }

        // ---- online softmax (rows r0, r0+8; quad-reduce) ----
        float mx0 = -1e30f, mx1 = -1e30f;
#pragma unroll
        for (int nt = 0; nt < 8; nt++) {
            mx0 = fmaxf(mx0, fmaxf(s[nt][0], s[nt][1]));
            mx1 = fmaxf(mx1, fmaxf(s[nt][2], s[nt][3]));
        }
#pragma unroll
        for (int off = 1; off < 4; off <<= 1) {
            mx0 = fmaxf(mx0, __shfl_xor_sync(0xffffffffu, mx0, off));
            mx1 = fmaxf(mx1, __shfl_xor_sync(0xffffffffu, mx1, off));
        }
        float mn0 = fmaxf(m0, mx0), mn1 = fmaxf(m1, mx1);
        float a0 = __expf(m0 - mn0), a1 = __expf(m1 - mn1);
        m0 = mn0; m1 = mn1;
        float ps0 = 0.0f, ps1 = 0.0f;
#pragma unroll
        for (int nt = 0; nt < 8; nt++) {
            s[nt][0] = __expf(s[nt][0] - mn0); ps0 += s[nt][0];
            s[nt][1] = __expf(s[nt][1] - mn0); ps0 += s[nt][1];
            s[nt][2] = __expf(s[nt][2] - mn1); ps1 += s[nt][2];
            s[nt][3] = __expf(s[nt][3] - mn1); ps1 += s[nt][3];
        }
#pragma unroll
        for (int off = 1; off < 4; off <<= 1) {
            ps0 += __shfl_xor_sync(0xffffffffu, ps0, off);
            ps1 += __shfl_xor_sync(0xffffffffu, ps1, off);
        }
        l0 = l0 * a0 + ps0;
        l1 = l1 * a1 + ps1;
#pragma unroll
        for (int nt = 0; nt < 8; nt++) {
            o_[nt][0] *= a0; o_[nt][1] *= a0;
            o_[nt][2] *= a1; o_[nt][3] *= a1;
        }

        // ---- re-pack P (S C-frags) into PV A-frags, bf16 hi/lo ----
        unsigned ph[4][4], pl[4][4];
#pragma unroll
        for (int ks = 0; ks < 4; ks++) {
            split2(s[2 * ks][0],     s[2 * ks][1],     ph[ks][0], pl[ks][0]);
            split2(s[2 * ks][2],     s[2 * ks][3],     ph[ks][1], pl[ks][1]);
            split2(s[2 * ks + 1][0], s[2 * ks + 1][1], ph[ks][2], pl[ks][2]);
            split2(s[2 * ks + 1][2], s[2 * ks + 1][3], ph[ks][3], pl[ks][3]);
        }

        // ---- O += P @ V (bf16x3) ----
#pragma unroll
        for (int nt = 0; nt < 8; nt++) {
            int base = (8 * nt + lq) * KST + 2 * lr;
#pragma unroll
            for (int ks = 0; ks < 4; ks++) {
                int o = base + 16 * ks;
                unsigned bh0 = *(const unsigned*)&Vh[o];
                unsigned bh1 = *(const unsigned*)&Vh[o + 8];
                unsigned bl0 = *(const unsigned*)&Vl[o];
                unsigned bl1 = *(const unsigned*)&Vl[o + 8];
                MMA_BF16(o_[nt], ph[ks], bh0, bh1);
                MMA_BF16(o_[nt], ph[ks], bl0, bl1);
                MMA_BF16(o_[nt], pl[ks], bh0, bh1);
            }
        }
        __syncthreads();   // tile consumed before next staging
    }

    // ---- write partial (unnormalized O, row max, row sum) ----
    float* PO = g_po + (size_t)slot * 64 * HS;
    int r0 = 16 * w + lq;
#pragma unroll
    for (int nt = 0; nt < 8; nt++) {
        int n = 8 * nt + 2 * lr;
        *(float2*)&PO[(size_t)r0 * HS + n]       = make_float2(o_[nt][0], o_[nt][1]);
        *(float2*)&PO[(size_t)(r0 + 8) * HS + n] = make_float2(o_[nt][2], o_[nt][3]);
    }
    if (lr == 0) {
        g_pm[(size_t)slot * 64 + r0]     = m0;
        g_pm[(size_t)slot * 64 + r0 + 8] = m1;
        g_pl[(size_t)slot * 64 + r0]     = l0;
        g_pl[(size_t)slot * 64 + r0 + 8] = l1;
    }
}

// ---------------------------------------------------------------------------
// Kernel 3: combine partials + epilogue /(l*8). 512 blocks (latency-bound
// at 128 before), 128 threads: r = 32*z + tid>>2, n0 = (tid&3)*16.
// ---------------------------------------------------------------------------
__global__ __launch_bounds__(128) void attn_reduce_kernel(float* __restrict__ out)
{
    const int qt  = blockIdx.x;
    const int b   = blockIdx.y;
    const int tid = threadIdx.x;
    const int r   = 32 * blockIdx.z + (tid >> 2);
    const int n0  = (tid & 3) * 16;

    const int nc = (qt >> 3) + 1;
    int pre = 0;
    for (int qq = 63; qq > qt; --qq) pre += (qq >> 3) + 1;
    const int gslot = b * NJOBS + pre;

    float m = -1e30f;
    for (int c = 0; c < nc; c++)
        m = fmaxf(m, g_pm[(size_t)(gslot + c) * 64 + r]);

    float lsum = 0.0f;
    float acc[16];
#pragma unroll
    for (int t = 0; t < 16; t++) acc[t] = 0.0f;

    for (int c = 0; c < nc; c++) {
        int slot = gslot + c;
        float wgt = __expf(g_pm[(size_t)slot * 64 + r] - m);
        lsum = fmaf(wgt, g_pl[(size_t)slot * 64 + r], lsum);
        const float* PO = g_po + ((size_t)slot * 64 + r) * HS + n0;
#pragma unroll
        for (int t = 0; t < 4; t++) {
            float4 v = *(const float4*)&PO[4 * t];
            acc[4 * t + 0] = fmaf(wgt, v.x, acc[4 * t + 0]);
            acc[4 * t + 1] = fmaf(wgt, v.y, acc[4 * t + 1]);
            acc[4 * t + 2] = fmaf(wgt, v.z, acc[4 * t + 2]);
            acc[4 * t + 3] = fmaf(wgt, v.w, acc[4 * t + 3]);
        }
    }

    // /(l) for softmax, /8 for the reference's post-softmax /sqrt(HS) quirk
    const float inv = 1.0f / (lsum * 8.0f);
    float* O = out + ((size_t)b * TSEQ + qt * 64 + r) * HS + n0;
#pragma unroll
    for (int t = 0; t < 4; t++) {
        float4 v = make_float4(acc[4 * t + 0] * inv, acc[4 * t + 1] * inv,
                               acc[4 * t + 2] * inv, acc[4 * t + 3] * inv);
        *(float4*)&O[4 * t] = v;
    }
}

// ---------------------------------------------------------------------------
extern "C" void kernel_launch(void* const* d_in, const int* in_sizes, int n_in,
                              void* d_out, int out_size)
{
    const float* X  = (const float*)d_in[0];
    const float* Wq = (const float*)d_in[1];
    const float* Wk = (const float*)d_in[2];
    const float* Wv = (const float*)d_in[3];
    float* out = (float*)d_out;

    (void)in_sizes; (void)n_in; (void)out_size;

    // W split+transpose to bf16 hi/lo
    wsplit_kernel<<<(3 * EMB * HS + 255) / 256, 256>>>(Wq, Wk, Wv);

    // Fused QKV projection on tensor cores (mma.sync)
    cudaFuncSetAttribute(qkv_kernel,
                         cudaFuncAttributeMaxDynamicSharedMemorySize, QKV_SMEM_BYTES);
    qkv_kernel<<<MTOT / 64, 128, QKV_SMEM_BYTES>>>(X);

    // Flash attention partials (BM=64, 3 CTAs/SM): 1152 blocks
    cudaFuncSetAttribute(attn_partial_kernel,
                         cudaFuncAttributeMaxDynamicSharedMemorySize, ATTN_SMEM_BYTES);
    attn_partial_kernel<<<NJOBS_T, 128, ATTN_SMEM_BYTES>>>();

    // Combine partials + epilogue (512 blocks: latency-bound at 128)
    dim3 g3(NQT, BATCH, 2);
    attn_reduce_kernel<<<g3, 128>>>(out);
}

// round 16
// speedup vs baseline: 1.0831x; 1.0831x over previous
#include <cuda_runtime.h>
#include <math.h>
#include <stdint.h>

#define EMB   1024
#define HS    64
#define TSEQ  4096
#define BATCH 4
#define MTOT  (BATCH * TSEQ)   // 16384 rows

#define NQT2   32              // 128-row q tiles per batch
#define CHUNK  8               // 64-row kv-tiles per partial job
#define NJOBS  144             // sum_{q=0}^{31} (q/4+1)
#define NJOBS_T (NJOBS * BATCH)

// Scratch (device globals: allocation-free rule)
__device__ unsigned short g_qh[MTOT * HS], g_ql[MTOT * HS];   // Q hi/lo bf16, natural
__device__ unsigned short g_kh[MTOT * HS], g_kl[MTOT * HS];   // K hi/lo bf16, natural
__device__ unsigned short g_vth[BATCH * HS * TSEQ];           // V hi bf16, transposed [b][h][t]
__device__ unsigned short g_vtl[BATCH * HS * TSEQ];           // V lo
__device__ unsigned short g_wth[3 * HS * EMB];                // W hi bf16, transposed [w][n][k]
__device__ unsigned short g_wtl[3 * HS * EMB];                // W lo
__device__ float g_po[NJOBS_T * 128 * HS];   // partial O [slot][row][64]
__device__ float g_pm[NJOBS_T * 128];        // partial row max
__device__ float g_pl[NJOBS_T * 128];        // partial row sum

// ---- bf16 split: pack (x,y) -> bf16x2 hi + lo residual ----
__device__ __forceinline__ void split2(float x, float y, unsigned &hp, unsigned &lp) {
    asm("cvt.rn.bf16x2.f32 %0, %1, %2;" : "=r"(hp) : "f"(y), "f"(x));
    float xh = __uint_as_float(hp << 16);
    float yh = __uint_as_float(hp & 0xffff0000u);
    asm("cvt.rn.bf16x2.f32 %0, %1, %2;" : "=r"(lp) : "f"(y - yh), "f"(x - xh));
}

// ---- warp mma m16n8k16 bf16 -> f32 accumulate ----
#define MMA_BF16(c, a, b0, b1) \
    asm("mma.sync.aligned.m16n8k16.row.col.f32.bf16.bf16.f32 " \
        "{%0,%1,%2,%3},{%4,%5,%6,%7},{%8,%9},{%0,%1,%2,%3};" \
        : "+f"((c)[0]), "+f"((c)[1]), "+f"((c)[2]), "+f"((c)[3]) \
        : "r"((a)[0]), "r"((a)[1]), "r"((a)[2]), "r"((a)[3]), "r"(b0), "r"(b1))

// ---- cp.async (16B) ----
#define CP_ASYNC16(s, g) \
    asm volatile("cp.async.cg.shared.global [%0], [%1], 16;" :: "r"(s), "l"(g))
#define CP_COMMIT() asm volatile("cp.async.commit_group;" ::: "memory")
#define CP_WAIT1()  asm volatile("cp.async.wait_group 1;" ::: "memory")
#define CP_WAIT0()  asm volatile("cp.async.wait_group 0;" ::: "memory")

__device__ __forceinline__ unsigned s2u(const void* p) {
    unsigned a;
    asm("{ .reg .u64 t; cvta.to.shared.u64 t, %1; cvt.u32.u64 %0, t; }"
        : "=r"(a) : "l"(p));
    return a;
}

// ---------------------------------------------------------------------------
// Kernel 0: split W into transposed bf16 hi/lo (verbatim R13).
// ---------------------------------------------------------------------------
__global__ __launch_bounds__(256) void wsplit_kernel(
    const float* __restrict__ Wq,
    const float* __restrict__ Wk,
    const float* __restrict__ Wv)
{
    int idx = blockIdx.x * 256 + threadIdx.x;
    if (idx >= 3 * EMB * HS) return;
    int w   = idx >> 16;
    int rem = idx & 65535;
    int k   = rem >> 6;
    int n   = rem & 63;
    const float* W = (w == 0) ? Wq : (w == 1) ? Wk : Wv;
    float x = W[k * HS + n];
    unsigned short h, l;
    asm("cvt.rn.bf16.f32 %0, %1;" : "=h"(h) : "f"(x));
    float xh = __uint_as_float(((unsigned)h) << 16);
    float xl = x - xh;
    asm("cvt.rn.bf16.f32 %0, %1;" : "=h"(l) : "f"(xl));
    g_wth[((size_t)w * HS + n) * EMB + k] = h;
    g_wtl[((size_t)w * HS + n) * EMB + k] = l;
}

// ---------------------------------------------------------------------------
// Kernel 1: fused QKV projection on tensor cores (verbatim R13 winner).
// ---------------------------------------------------------------------------
#define XKS 72
#define QKV_SMEM_BYTES ((2 * 64 * XKS + 2 * 3 * 64 * XKS) * 2)

__global__ __launch_bounds__(128, 2) void qkv_kernel(const float* __restrict__ X)
{
    extern __shared__ __align__(16) unsigned short sm[];
    unsigned short* Xh = sm;
    unsigned short* Xl = Xh + 64 * XKS;
    unsigned short* Wh = Xl + 64 * XKS;
    unsigned short* Wl = Wh + 3 * 64 * XKS;

    const int tid  = threadIdx.x;
    const int wid  = tid >> 5;
    const int lane = tid & 31;
    const int lq   = lane >> 2;
    const int lr   = lane & 3;
    const int m0   = blockIdx.x * 64;

    float c[3][8][4];
#pragma unroll
    for (int w3 = 0; w3 < 3; w3++)
#pragma unroll
        for (int nt = 0; nt < 8; nt++)
#pragma unroll
            for (int j = 0; j < 4; j++) c[w3][nt][j] = 0.0f;

    for (int k0 = 0; k0 < EMB; k0 += 64) {
#pragma unroll
        for (int t = 0; t < 8; t++) {
            int idx = tid + 128 * t;
            int row = idx >> 4;
            int cg  = idx & 15;
            float4 v = *(const float4*)&X[(size_t)(m0 + row) * EMB + k0 + 4 * cg];
            unsigned h01, l01, h23, l23;
            split2(v.x, v.y, h01, l01);
            split2(v.z, v.w, h23, l23);
            *(unsigned*)&Xh[row * XKS + 4 * cg]     = h01;
            *(unsigned*)&Xh[row * XKS + 4 * cg + 2] = h23;
            *(unsigned*)&Xl[row * XKS + 4 * cg]     = l01;
            *(unsigned*)&Xl[row * XKS + 4 * cg + 2] = l23;
        }
#pragma unroll
        for (int t = 0; t < 24; t++) {
            int idx  = tid + 128 * t;
            int wh   = idx >> 9;
            int w3   = wh >> 1;
            int half = wh & 1;
            int rem  = idx & 511;
            int n    = rem >> 3;
            int cc   = rem & 7;
            const unsigned short* src = half ? g_wtl : g_wth;
            unsigned short* dst = half ? Wl : Wh;
            *(float4*)&dst[(w3 * 64 + n) * XKS + 8 * cc] =
                *(const float4*)&src[((size_t)w3 * 64 + n) * EMB + k0 + 8 * cc];
        }
        __syncthreads();

        unsigned ah[4][4], al[4][4];
        int r = 16 * wid + lq;
#pragma unroll
        for (int ks = 0; ks < 4; ks++) {
            int col = 2 * lr + 16 * ks;
            ah[ks][0] = *(const unsigned*)&Xh[r * XKS + col];
            ah[ks][1] = *(const unsigned*)&Xh[(r + 8) * XKS + col];
            ah[ks][2] = *(const unsigned*)&Xh[r * XKS + col + 8];
            ah[ks][3] = *(const unsigned*)&Xh[(r + 8) * XKS + col + 8];
            al[ks][0] = *(const unsigned*)&Xl[r * XKS + col];
            al[ks][1] = *(const unsigned*)&Xl[(r + 8) * XKS + col];
            al[ks][2] = *(const unsigned*)&Xl[r * XKS + col + 8];
            al[ks][3] = *(const unsigned*)&Xl[(r + 8) * XKS + col + 8];
        }

#pragma unroll
        for (int w3 = 0; w3 < 3; w3++)
#pragma unroll
            for (int nt = 0; nt < 8; nt++)
#pragma unroll
                for (int ks = 0; ks < 4; ks++) {
                    int base = (w3 * 64 + 8 * nt + lq) * XKS + 2 * lr + 16 * ks;
                    unsigned bh0 = *(const unsigned*)&Wh[base];
                    unsigned bh1 = *(const unsigned*)&Wh[base + 8];
                    unsigned bl0 = *(const unsigned*)&Wl[base];
                    unsigned bl1 = *(const unsigned*)&Wl[base + 8];
                    MMA_BF16(c[w3][nt], ah[ks], bh0, bh1);
                    MMA_BF16(c[w3][nt], ah[ks], bl0, bl1);
                    MMA_BF16(c[w3][nt], al[ks], bh0, bh1);
                }
        __syncthreads();
    }

    const int r0 = m0 + 16 * wid + lq;
    const int bb = r0 >> 12;
    const int t0 = r0 & 4095;
#pragma unroll
    for (int nt = 0; nt < 8; nt++) {
        int n0 = 8 * nt + 2 * lr;
        unsigned hp, lp;
        split2(c[0][nt][0], c[0][nt][1], hp, lp);
        *(unsigned*)&g_qh[(size_t)r0 * HS + n0] = hp;
        *(unsigned*)&g_ql[(size_t)r0 * HS + n0] = lp;
        split2(c[0][nt][2], c[0][nt][3], hp, lp);
        *(unsigned*)&g_qh[(size_t)(r0 + 8) * HS + n0] = hp;
        *(unsigned*)&g_ql[(size_t)(r0 + 8) * HS + n0] = lp;
        split2(c[1][nt][0], c[1][nt][1], hp, lp);
        *(unsigned*)&g_kh[(size_t)r0 * HS + n0] = hp;
        *(unsigned*)&g_kl[(size_t)r0 * HS + n0] = lp;
        split2(c[1][nt][2], c[1][nt][3], hp, lp);
        *(unsigned*)&g_kh[(size_t)(r0 + 8) * HS + n0] = hp;
        *(unsigned*)&g_kl[(size_t)(r0 + 8) * HS + n0] = lp;
        split2(c[2][nt][0], c[2][nt][1], hp, lp);
        g_vth[((size_t)bb * HS + n0) * TSEQ + t0]     = (unsigned short)hp;
        g_vth[((size_t)bb * HS + n0 + 1) * TSEQ + t0] = (unsigned short)(hp >> 16);
        g_vtl[((size_t)bb * HS + n0) * TSEQ + t0]     = (unsigned short)lp;
        g_vtl[((size_t)bb * HS + n0 + 1) * TSEQ + t0] = (unsigned short)(lp >> 16);
        split2(c[2][nt][2], c[2][nt][3], hp, lp);
        g_vth[((size_t)bb * HS + n0) * TSEQ + t0 + 8]     = (unsigned short)hp;
        g_vth[((size_t)bb * HS + n0 + 1) * TSEQ + t0 + 8] = (unsigned short)(hp >> 16);
        g_vtl[((size_t)bb * HS + n0) * TSEQ + t0 + 8]     = (unsigned short)lp;
        g_vtl[((size_t)bb * HS + n0 + 1) * TSEQ + t0 + 8] = (unsigned short)(lp >> 16);
    }
}

// ---------------------------------------------------------------------------
// Kernel 2: split-KV flash attention (R13 BM=128 shape) + cp.async
// double-buffered K/V staging. 256 threads = 8 warps; warp w owns rows
// [16w,16w+16). Buffers: [2][4 arrays][64][KST] ushorts.
// ---------------------------------------------------------------------------
#define KST 72                           // ushort stride of K/Vt smem rows
#define ARRB (64 * KST * 2)              // bytes per array  (9216)
#define BUFB (4 * ARRB)                  // bytes per buffer (36864)
#define ATTN_SMEM_BYTES (2 * BUFB)       // 73728

__global__ __launch_bounds__(256, 2) void attn_partial_kernel(void)
{
    extern __shared__ __align__(16) unsigned short smh[];
    const unsigned sbase = s2u(smh);

    const int b = blockIdx.x & 3;
    int rem = blockIdx.x >> 2;
    int q = 31;
    for (;;) { int nc = (q >> 2) + 1; if (rem < nc) break; rem -= nc; --q; }
    const int qt2 = q;
    const int c = rem;
    const int kt0 = CHUNK * c;
    const int kt1 = min(CHUNK * c + CHUNK, 2 * qt2 + 2);
    int pre = 0;
    for (int qq = 31; qq > qt2; --qq) pre += (qq >> 2) + 1;
    const int slot = b * NJOBS + pre + c;

    const int tid  = threadIdx.x;
    const int w    = tid >> 5;
    const int lane = tid & 31;
    const int lq   = lane >> 2;    // 0..7
    const int lr   = lane & 3;     // 0..3

    const size_t qrow0 = (size_t)b * TSEQ + qt2 * 128 + 16 * w + lq;
    const size_t kbase = (size_t)b * TSEQ;

    // staging indices for this thread (2 x 4 cp.asyncs per tile)
    const int srow0 = tid >> 3;          // 0..31  (idx = tid)
    const int scc0  = tid & 7;
    const int srow1 = (tid + 256) >> 3;  // 32..63
    const int scc1  = scc0;

    // ---- load Q fragments (hi/lo) once ----
    unsigned ah[4][4], al[4][4];
#pragma unroll
    for (int ks = 0; ks < 4; ks++) {
        int col = 2 * lr + 16 * ks;
        ah[ks][0] = *(const unsigned*)&g_qh[qrow0 * HS + col];
        ah[ks][1] = *(const unsigned*)&g_qh[(qrow0 + 8) * HS + col];
        ah[ks][2] = *(const unsigned*)&g_qh[qrow0 * HS + col + 8];
        ah[ks][3] = *(const unsigned*)&g_qh[(qrow0 + 8) * HS + col + 8];
        al[ks][0] = *(const unsigned*)&g_ql[qrow0 * HS + col];
        al[ks][1] = *(const unsigned*)&g_ql[(qrow0 + 8) * HS + col];
        al[ks][2] = *(const unsigned*)&g_ql[qrow0 * HS + col + 8];
        al[ks][3] = *(const unsigned*)&g_ql[(qrow0 + 8) * HS + col + 8];
    }

    float m0 = -1e30f, m1 = -1e30f, l0 = 0.0f, l1 = 0.0f;
    float o_[8][4];
#pragma unroll
    for (int nt = 0; nt < 8; nt++)
#pragma unroll
        for (int j = 0; j < 4; j++) o_[nt][j] = 0.0f;

    // ---- prefetch helper (macro to keep addresses simple) ----
#define STAGE_TILE(bufsel, ktv) do {                                          \
    unsigned dbase = sbase + (bufsel) * BUFB;                                 \
    {                                                                         \
        unsigned off = srow0 * (KST * 2) + 16 * scc0;                         \
        size_t kg = (kbase + (size_t)(ktv) * 64 + srow0) * HS + 8 * scc0;     \
        size_t vg = ((size_t)(b * HS + srow0)) * TSEQ + (size_t)(ktv) * 64 + 8 * scc0; \
        CP_ASYNC16(dbase + 0 * ARRB + off, (const char*)&g_kh[kg]);           \
        CP_ASYNC16(dbase + 1 * ARRB + off, (const char*)&g_kl[kg]);           \
        CP_ASYNC16(dbase + 2 * ARRB + off, (const char*)&g_vth[vg]);          \
        CP_ASYNC16(dbase + 3 * ARRB + off, (const char*)&g_vtl[vg]);          \
    }                                                                         \
    {                                                                         \
        unsigned off = srow1 * (KST * 2) + 16 * scc1;                         \
        size_t kg = (kbase + (size_t)(ktv) * 64 + srow1) * HS + 8 * scc1;     \
        size_t vg = ((size_t)(b * HS + srow1)) * TSEQ + (size_t)(ktv) * 64 + 8 * scc1; \
        CP_ASYNC16(dbase + 0 * ARRB + off, (const char*)&g_kh[kg]);           \
        CP_ASYNC16(dbase + 1 * ARRB + off, (const char*)&g_kl[kg]);           \
        CP_ASYNC16(dbase + 2 * ARRB + off, (const char*)&g_vth[vg]);          \
        CP_ASYNC16(dbase + 3 * ARRB + off, (const char*)&g_vtl[vg]);          \
    }                                                                         \
} while (0)

    // prime pipeline
    STAGE_TILE(0, kt0);
    CP_COMMIT();

    int buf = 0;
    for (int kt = kt0; kt < kt1; kt++) {
        // prefetch next tile into the other buffer, then retire current
        if (kt + 1 < kt1) {
            STAGE_TILE(buf ^ 1, kt + 1);
            CP_COMMIT();
            CP_WAIT1();
        } else {
            CP_WAIT0();
        }
        __syncthreads();

        const unsigned short* Kh = smh + buf * (BUFB / 2);            // ushort idx
        const unsigned short* Kl = Kh + 64 * KST;
        const unsigned short* Vh = Kl + 64 * KST;
        const unsigned short* Vl = Vh + 64 * KST;

        bool active = !(kt == 2 * qt2 + 1 && w < 4);
        if (active) {
            float s[8][4];
#pragma unroll
            for (int nt = 0; nt < 8; nt++)
#pragma unroll
                for (int j = 0; j < 4; j++) s[nt][j] = 0.0f;

#pragma unroll
            for (int nt = 0; nt < 8; nt++) {
                int base = (8 * nt + lq) * KST + 2 * lr;
#pragma unroll
                for (int ks = 0; ks < 4; ks++) {
                    int o = base + 16 * ks;
                    unsigned bh0 = *(const unsigned*)&Kh[o];
                    unsigned bh1 = *(const unsigned*)&Kh[o + 8];
                    unsigned bl0 = *(const unsigned*)&Kl[o];
                    unsigned bl1 = *(const unsigned*)&Kl[o + 8];
                    MMA_BF16(s[nt], ah[ks], bh0, bh1);
                    MMA_BF16(s[nt], ah[ks], bl0, bl1);
                    MMA_BF16(s[nt], al[ks], bh0, bh1);
                }
            }

            if (kt >= 2 * qt2) {
                int off = (kt - 2 * qt2) * 64;
                int rl0 = 16 * w + lq;
                int rl1 = rl0 + 8;
#pragma unroll
                for (int nt = 0; nt < 8; nt++) {
                    int cl = off + 8 * nt + 2 * lr;
                    if (cl     > rl0) s[nt][0] = -1e30f;
                    if (cl + 1 > rl0) s[nt][1] = -1e30f;
                    if (cl     > rl1) s[nt][2] = -1e30f;
                    if (cl + 1 > rl1) s[nt][3] = -1e30f;
                }
            }

            float mx0 = -1e30f, mx1 = -1e30f;
#pragma unroll
            for (int nt = 0; nt < 8; nt++) {
                mx0 = fmaxf(mx0, fmaxf(s[nt][0], s[nt][1]));
                mx1 = fmaxf(mx1, fmaxf(s[nt][2], s[nt][3]));
            }
#pragma unroll
            for (int off = 1; off < 4; off <<= 1) {
                mx0 = fmaxf(mx0, __shfl_xor_sync(0xffffffffu, mx0, off));
                mx1 = fmaxf(mx1, __shfl_xor_sync(0xffffffffu, mx1, off));
            }
            float mn0 = fmaxf(m0, mx0), mn1 = fmaxf(m1, mx1);
            float a0 = __expf(m0 - mn0), a1 = __expf(m1 - mn1);
            m0 = mn0; m1 = mn1;
            float ps0 = 0.0f, ps1 = 0.0f;
#pragma unroll
            for (int nt = 0; nt < 8; nt++) {
                s[nt][0] = __expf(s[nt][0] - mn0); ps0 += s[nt][0];
                s[nt][1] = __expf(s[nt][1] - mn0); ps0 += s[nt][1];
                s[nt][2] = __expf(s[nt][2] - mn1); ps1 += s[nt][2];
                s[nt][3] = __expf(s[nt][3] - mn1); ps1 += s[nt][3];
            }
#pragma unroll
            for (int off = 1; off < 4; off <<= 1) {
                ps0 += __shfl_xor_sync(0xffffffffu, ps0, off);
                ps1 += __shfl_xor_sync(0xffffffffu, ps1, off);
            }
            l0 = l0 * a0 + ps0;
            l1 = l1 * a1 + ps1;
#pragma unroll
            for (int nt = 0; nt < 8; nt++) {
                o_[nt][0] *= a0; o_[nt][1] *= a0;
                o_[nt][2] *= a1; o_[nt][3] *= a1;
            }

            unsigned ph[4][4], pl[4][4];
#pragma unroll
            for (int ks = 0; ks < 4; ks++) {
                split2(s[2 * ks][0],     s[2 * ks][1],     ph[ks][0], pl[ks][0]);
                split2(s[2 * ks][2],     s[2 * ks][3],     ph[ks][1], pl[ks][1]);
                split2(s[2 * ks + 1][0], s[2 * ks + 1][1], ph[ks][2], pl[ks][2]);
                split2(s[2 * ks + 1][2], s[2 * ks + 1][3], ph[ks][3], pl[ks][3]);
            }

#pragma unroll
            for (int nt = 0; nt < 8; nt++) {
                int base = (8 * nt + lq) * KST + 2 * lr;
#pragma unroll
                for (int ks = 0; ks < 4; ks++) {
                    int o = base + 16 * ks;
                    unsigned bh0 = *(const unsigned*)&Vh[o];
                    unsigned bh1 = *(const unsigned*)&Vh[o + 8];
                    unsigned bl0 = *(const unsigned*)&Vl[o];
                    unsigned bl1 = *(const unsigned*)&Vl[o + 8];
                    MMA_BF16(o_[nt], ph[ks], bh0, bh1);
                    MMA_BF16(o_[nt], ph[ks], bl0, bl1);
                    MMA_BF16(o_[nt], pl[ks], bh0, bh1);
                }
            }
        }
        __syncthreads();   // all reads of buf done before it's re-staged
        buf ^= 1;
    }
#undef STAGE_TILE

    float* PO = g_po + (size_t)slot * 128 * HS;
    int r0 = 16 * w + lq;
#pragma unroll
    for (int nt = 0; nt < 8; nt++) {
        int n = 8 * nt + 2 * lr;
        *(float2*)&PO[(size_t)r0 * HS + n]       = make_float2(o_[nt][0], o_[nt][1]);
        *(float2*)&PO[(size_t)(r0 + 8) * HS + n] = make_float2(o_[nt][2], o_[nt][3]);
    }
    if (lr == 0) {
        g_pm[(size_t)slot * 128 + r0]     = m0;
        g_pm[(size_t)slot * 128 + r0 + 8] = m1;
        g_pl[(size_t)slot * 128 + r0]     = l0;
        g_pl[(size_t)slot * 128 + r0 + 8] = l1;
    }
}

// ---------------------------------------------------------------------------
// Kernel 3: combine partials + epilogue /(l*8). 512 blocks (latency fix,
// measured 16.6 -> 12.4 us). r = 32*z + tid>>2, n0 = (tid&3)*16.
// ---------------------------------------------------------------------------
__global__ __launch_bounds__(128) void attn_reduce_kernel(float* __restrict__ out)
{
    const int qt2 = blockIdx.x;
    const int b   = blockIdx.y;
    const int tid = threadIdx.x;
    const int r   = 32 * blockIdx.z + (tid >> 2);
    const int n0  = (tid & 3) * 16;

    const int nc = (qt2 >> 2) + 1;
    int pre = 0;
    for (int qq = 31; qq > qt2; --qq) pre += (qq >> 2) + 1;
    const int gslot = b * NJOBS + pre;

    float m = -1e30f;
    for (int c = 0; c < nc; c++)
        m = fmaxf(m, g_pm[(size_t)(gslot + c) * 128 + r]);

    float lsum = 0.0f;
    float acc[16];
#pragma unroll
    for (int t = 0; t < 16; t++) acc[t] = 0.0f;

    for (int c = 0; c < nc; c++) {
        int slot = gslot + c;
        float wgt = __expf(g_pm[(size_t)slot * 128 + r] - m);
        lsum = fmaf(wgt, g_pl[(size_t)slot * 128 + r], lsum);
        const float* PO = g_po + ((size_t)slot * 128 + r) * HS + n0;
#pragma unroll
        for (int t = 0; t < 4; t++) {
            float4 v = *(const float4*)&PO[4 * t];
            acc[4 * t + 0] = fmaf(wgt, v.x, acc[4 * t + 0]);
            acc[4 * t + 1] = fmaf(wgt, v.y, acc[4 * t + 1]);
            acc[4 * t + 2] = fmaf(wgt, v.z, acc[4 * t + 2]);
            acc[4 * t + 3] = fmaf(wgt, v.w, acc[4 * t + 3]);
        }
    }

    // /(l) for softmax, /8 for the reference's post-softmax /sqrt(HS) quirk
    const float inv = 1.0f / (lsum * 8.0f);
    float* O = out + ((size_t)b * TSEQ + qt2 * 128 + r) * HS + n0;
#pragma unroll
    for (int t = 0; t < 4; t++) {
        float4 v = make_float4(acc[4 * t + 0] * inv, acc[4 * t + 1] * inv,
                               acc[4 * t + 2] * inv, acc[4 * t + 3] * inv);
        *(float4*)&O[4 * t] = v;
    }
}

// ---------------------------------------------------------------------------
extern "C" void kernel_launch(void* const* d_in, const int* in_sizes, int n_in,
                              void* d_out, int out_size)
{
    const float* X  = (const float*)d_in[0];
    const float* Wq = (const float*)d_in[1];
    const float* Wk = (const float*)d_in[2];
    const float* Wv = (const float*)d_in[3];
    float* out = (float*)d_out;

    (void)in_sizes; (void)n_in; (void)out_size;

    // W split+transpose to bf16 hi/lo
    wsplit_kernel<<<(3 * EMB * HS + 255) / 256, 256>>>(Wq, Wk, Wv);

    // Fused QKV projection on tensor cores (mma.sync)
    cudaFuncSetAttribute(qkv_kernel,
                         cudaFuncAttributeMaxDynamicSharedMemorySize, QKV_SMEM_BYTES);
    qkv_kernel<<<MTOT / 64, 128, QKV_SMEM_BYTES>>>(X);

    // Flash attention partials (BM=128, cp.async double-buffered)
    cudaFuncSetAttribute(attn_partial_kernel,
                         cudaFuncAttributeMaxDynamicSharedMemorySize, ATTN_SMEM_BYTES);
    attn_partial_kernel<<<NJOBS_T, 256, ATTN_SMEM_BYTES>>>();

    // Combine partials + epilogue (512 blocks)
    dim3 g3(NQT2, BATCH, 4);
    attn_reduce_kernel<<<g3, 128>>>(out);
}